// round 1
// baseline (speedup 1.0000x reference)
#include <cuda_runtime.h>
#include <math_constants.h>

// Problem constants
namespace {
constexpr int B_  = 4;
constexpr int S_  = 2048;
constexpr int D_  = 1024;
constexpr int H_  = 16;
constexpr int DK_ = 64;
constexpr int M_  = B_ * S_;  // 8192 rows for projection GEMMs
constexpr long long OUT_ELEMS  = (long long)B_ * S_ * D_;        // 8388608
constexpr long long ATTN_ELEMS = (long long)B_ * H_ * S_ * S_;   // 268435456
constexpr int QPAD = 68;  // row pitch (floats) for 64-wide smem tiles, 16B aligned
}

// Scratch (device globals: allocation-free rule)
__device__ float g_q[B_ * S_ * D_];
__device__ float g_k[B_ * S_ * D_];
__device__ float g_v[B_ * S_ * D_];
__device__ float g_ctx[B_ * S_ * D_];
__device__ float g_m[B_ * H_ * S_];
__device__ float g_l[B_ * H_ * S_];

// ---------------------------------------------------------------------------
// C[M,N] = A[M,K] @ W[N,K]^T + bias[N]   (torch Linear convention)
// 64x64 block tile, BK=16, 256 threads, 4x4 register microtile per thread.
// ---------------------------------------------------------------------------
__global__ void __launch_bounds__(256) sgemm_bias_kernel(
    const float* __restrict__ A, const float* __restrict__ W,
    const float* __restrict__ bias, float* __restrict__ C,
    int M, int N, int K)
{
    __shared__ float As[16][QPAD];
    __shared__ float Bs[16][QPAD];

    const int tid = threadIdx.x;
    const int bm  = blockIdx.y * 64;
    const int bn  = blockIdx.x * 64;
    const int tx  = tid & 15;
    const int ty  = tid >> 4;
    const int lrow = tid >> 2;         // 0..63
    const int lk4  = (tid & 3) << 2;   // 0,4,8,12

    const float* Ap = A + (size_t)(bm + lrow) * K + lk4;
    const float* Wp = W + (size_t)(bn + lrow) * K + lk4;

    float acc[4][4] = {};

    for (int k0 = 0; k0 < K; k0 += 16) {
        float4 av = *(const float4*)(Ap + k0);
        float4 wv = *(const float4*)(Wp + k0);
        __syncthreads();
        As[lk4 + 0][lrow] = av.x; As[lk4 + 1][lrow] = av.y;
        As[lk4 + 2][lrow] = av.z; As[lk4 + 3][lrow] = av.w;
        Bs[lk4 + 0][lrow] = wv.x; Bs[lk4 + 1][lrow] = wv.y;
        Bs[lk4 + 2][lrow] = wv.z; Bs[lk4 + 3][lrow] = wv.w;
        __syncthreads();
#pragma unroll
        for (int kk = 0; kk < 16; ++kk) {
            float a[4], b[4];
#pragma unroll
            for (int i = 0; i < 4; ++i) a[i] = As[kk][ty * 4 + i];
#pragma unroll
            for (int j = 0; j < 4; ++j) b[j] = Bs[kk][tx * 4 + j];
#pragma unroll
            for (int i = 0; i < 4; ++i)
#pragma unroll
                for (int j = 0; j < 4; ++j)
                    acc[i][j] = fmaf(a[i], b[j], acc[i][j]);
        }
    }

    float bvv[4];
#pragma unroll
    for (int j = 0; j < 4; ++j) bvv[j] = bias[bn + tx * 4 + j];
#pragma unroll
    for (int i = 0; i < 4; ++i) {
        float4 o;
        o.x = acc[i][0] + bvv[0];
        o.y = acc[i][1] + bvv[1];
        o.z = acc[i][2] + bvv[2];
        o.w = acc[i][3] + bvv[3];
        *(float4*)(C + (size_t)(bm + ty * 4 + i) * N + bn + tx * 4) = o;
    }
}

// ---------------------------------------------------------------------------
// Pass A: per-row softmax stats (m = rowmax, l = sum exp) flash-style.
// Block = (q-tile of 64 rows, head h, batch b); 256 threads.
// Thread (ty,tx): rows ty*4..+3, keys tx*4..+3 within each 64-key chunk.
// ---------------------------------------------------------------------------
__global__ void __launch_bounds__(256) attn_stats_kernel(
    const float* __restrict__ qg, const float* __restrict__ kg,
    const int* __restrict__ maskg,
    float* __restrict__ mg, float* __restrict__ lg)
{
    extern __shared__ float sm[];
    float* Qs = sm;                 // 64 x QPAD
    float* Ks = sm + 64 * QPAD;     // 64 x QPAD
    __shared__ int msk[64];

    const int qt  = blockIdx.x;
    const int h   = blockIdx.y;
    const int b   = blockIdx.z;
    const int tid = threadIdx.x;
    const int q0  = qt * 64;

    // Load Q tile (64 rows x 64 cols of head h)
#pragma unroll
    for (int it = 0; it < 4; ++it) {
        int f = it * 256 + tid;
        int r = f >> 4, c4 = (f & 15) << 2;
        float4 v = *(const float4*)(qg + ((size_t)(b * S_ + q0 + r)) * D_ + h * DK_ + c4);
        *(float4*)(Qs + r * QPAD + c4) = v;
    }

    const int tx = tid & 15, ty = tid >> 4;
    const int r0 = ty * 4,   c0 = tx * 4;

    float m[4], l[4];
#pragma unroll
    for (int i = 0; i < 4; ++i) { m[i] = -CUDART_INF_F; l[i] = 0.f; }

    for (int kt = 0; kt < S_ / 64; ++kt) {
        const int kb = kt * 64;
        __syncthreads();
#pragma unroll
        for (int it = 0; it < 4; ++it) {
            int f = it * 256 + tid;
            int r = f >> 4, c4 = (f & 15) << 2;
            *(float4*)(Ks + r * QPAD + c4) =
                *(const float4*)(kg + ((size_t)(b * S_ + kb + r)) * D_ + h * DK_ + c4);
        }
        if (tid < 64) msk[tid] = maskg[b * S_ + kb + tid];
        __syncthreads();

        float s[4][4] = {};
#pragma unroll 8
        for (int kk = 0; kk < 64; ++kk) {
            float a[4], bb[4];
#pragma unroll
            for (int i = 0; i < 4; ++i) a[i] = Qs[(r0 + i) * QPAD + kk];
#pragma unroll
            for (int j = 0; j < 4; ++j) bb[j] = Ks[(c0 + j) * QPAD + kk];
#pragma unroll
            for (int i = 0; i < 4; ++i)
#pragma unroll
                for (int j = 0; j < 4; ++j)
                    s[i][j] = fmaf(a[i], bb[j], s[i][j]);
        }

#pragma unroll
        for (int i = 0; i < 4; ++i) {
            float sv[4];
#pragma unroll
            for (int j = 0; j < 4; ++j) {
                float sc = s[i][j] * 0.125f;  // 1/sqrt(64)
                sv[j] = (msk[c0 + j] != 0) ? sc : -CUDART_INF_F;
            }
            float rmax = fmaxf(fmaxf(sv[0], sv[1]), fmaxf(sv[2], sv[3]));
#pragma unroll
            for (int off = 8; off >= 1; off >>= 1)
                rmax = fmaxf(rmax, __shfl_xor_sync(0xffffffffu, rmax, off, 16));
            float nm = fmaxf(m[i], rmax);
            float sum = 0.f;
#pragma unroll
            for (int j = 0; j < 4; ++j)
                sum += (msk[c0 + j] != 0) ? __expf(sv[j] - nm) : 0.f;
#pragma unroll
            for (int off = 8; off >= 1; off >>= 1)
                sum += __shfl_xor_sync(0xffffffffu, sum, off, 16);
            float alpha = (m[i] == -CUDART_INF_F) ? 0.f : __expf(m[i] - nm);
            l[i] = l[i] * alpha + sum;
            m[i] = nm;
        }
    }

    if (tx == 0) {
#pragma unroll
        for (int i = 0; i < 4; ++i) {
            int idx = (b * H_ + h) * S_ + q0 + r0 + i;
            mg[idx] = m[i];
            lg[idx] = l[i];
        }
    }
}

// ---------------------------------------------------------------------------
// Pass B: recompute scores, write normalized attn (optional), and fuse
// ctx = attn @ V into register accumulators.
// ---------------------------------------------------------------------------
__global__ void __launch_bounds__(256) attn_apply_kernel(
    const float* __restrict__ qg, const float* __restrict__ kg,
    const float* __restrict__ vg, const int* __restrict__ maskg,
    const float* __restrict__ mg, const float* __restrict__ lg,
    float* __restrict__ attn, float* __restrict__ ctx)
{
    extern __shared__ float sm[];
    float* Qs = sm;
    float* Ks = sm + 1 * 64 * QPAD;
    float* Vs = sm + 2 * 64 * QPAD;
    float* Ps = sm + 3 * 64 * QPAD;
    __shared__ int msk[64];

    const int qt  = blockIdx.x;
    const int h   = blockIdx.y;
    const int b   = blockIdx.z;
    const int tid = threadIdx.x;
    const int q0  = qt * 64;

#pragma unroll
    for (int it = 0; it < 4; ++it) {
        int f = it * 256 + tid;
        int r = f >> 4, c4 = (f & 15) << 2;
        float4 v = *(const float4*)(qg + ((size_t)(b * S_ + q0 + r)) * D_ + h * DK_ + c4);
        *(float4*)(Qs + r * QPAD + c4) = v;
    }

    const int tx = tid & 15, ty = tid >> 4;
    const int r0 = ty * 4,   c0 = tx * 4;

    float mrow[4], invl[4];
#pragma unroll
    for (int i = 0; i < 4; ++i) {
        int idx = (b * H_ + h) * S_ + q0 + r0 + i;
        mrow[i] = mg[idx];
        float lv = lg[idx];
        invl[i] = (lv > 0.f) ? (1.f / lv) : 0.f;
    }

    float acc[4][4] = {};

    for (int kt = 0; kt < S_ / 64; ++kt) {
        const int kb = kt * 64;
        __syncthreads();
#pragma unroll
        for (int it = 0; it < 4; ++it) {
            int f = it * 256 + tid;
            int r = f >> 4, c4 = (f & 15) << 2;
            size_t base = ((size_t)(b * S_ + kb + r)) * D_ + h * DK_ + c4;
            *(float4*)(Ks + r * QPAD + c4) = *(const float4*)(kg + base);
            *(float4*)(Vs + r * QPAD + c4) = *(const float4*)(vg + base);
        }
        if (tid < 64) msk[tid] = maskg[b * S_ + kb + tid];
        __syncthreads();

        float s[4][4] = {};
#pragma unroll 8
        for (int kk = 0; kk < 64; ++kk) {
            float a[4], bb[4];
#pragma unroll
            for (int i = 0; i < 4; ++i) a[i] = Qs[(r0 + i) * QPAD + kk];
#pragma unroll
            for (int j = 0; j < 4; ++j) bb[j] = Ks[(c0 + j) * QPAD + kk];
#pragma unroll
            for (int i = 0; i < 4; ++i)
#pragma unroll
                for (int j = 0; j < 4; ++j)
                    s[i][j] = fmaf(a[i], bb[j], s[i][j]);
        }

#pragma unroll
        for (int i = 0; i < 4; ++i) {
            float p[4];
#pragma unroll
            for (int j = 0; j < 4; ++j) {
                float sc = s[i][j] * 0.125f;
                p[j] = (msk[c0 + j] != 0) ? (__expf(sc - mrow[i]) * invl[i]) : 0.f;
            }
            float4 pv = make_float4(p[0], p[1], p[2], p[3]);
            *(float4*)(Ps + (r0 + i) * QPAD + c0) = pv;
            if (attn) {
                *(float4*)(attn + ((size_t)(b * H_ + h) * S_ + q0 + r0 + i) * S_ + kb + c0) = pv;
            }
        }
        __syncthreads();

        // ctx tile += P (64x64) @ V (64x64); thread owns rows r0..+3, dims c0..+3
#pragma unroll 8
        for (int c = 0; c < 64; ++c) {
            float a[4], vv[4];
#pragma unroll
            for (int i = 0; i < 4; ++i) a[i] = Ps[(r0 + i) * QPAD + c];
#pragma unroll
            for (int j = 0; j < 4; ++j) vv[j] = Vs[c * QPAD + c0 + j];
#pragma unroll
            for (int i = 0; i < 4; ++i)
#pragma unroll
                for (int j = 0; j < 4; ++j)
                    acc[i][j] = fmaf(a[i], vv[j], acc[i][j]);
        }
    }

#pragma unroll
    for (int i = 0; i < 4; ++i) {
        float4 o = make_float4(acc[i][0], acc[i][1], acc[i][2], acc[i][3]);
        *(float4*)(ctx + ((size_t)(b * S_ + q0 + r0 + i)) * D_ + h * DK_ + c0) = o;
    }
}

// ---------------------------------------------------------------------------
extern "C" void kernel_launch(void* const* d_in, const int* in_sizes, int n_in,
                              void* d_out, int out_size)
{
    const float* hs   = (const float*)d_in[0];
    const int*   mask = (const int*)  d_in[1];
    const float* Wq   = (const float*)d_in[2];
    const float* bq   = (const float*)d_in[3];
    const float* Wk   = (const float*)d_in[4];
    const float* bk   = (const float*)d_in[5];
    const float* Wv   = (const float*)d_in[6];
    const float* bv   = (const float*)d_in[7];
    const float* Wo   = (const float*)d_in[8];
    const float* bo   = (const float*)d_in[9];

    float* outp = (float*)d_out;

    float *qp, *kp, *vp, *ctxp, *mp, *lp;
    cudaGetSymbolAddress((void**)&qp,   g_q);
    cudaGetSymbolAddress((void**)&kp,   g_k);
    cudaGetSymbolAddress((void**)&vp,   g_v);
    cudaGetSymbolAddress((void**)&ctxp, g_ctx);
    cudaGetSymbolAddress((void**)&mp,   g_m);
    cudaGetSymbolAddress((void**)&lp,   g_l);

    float* attnp = nullptr;
    if ((long long)out_size >= OUT_ELEMS + ATTN_ELEMS)
        attnp = outp + OUT_ELEMS;

    dim3 gg(D_ / 64, M_ / 64);   // (16, 128)
    sgemm_bias_kernel<<<gg, 256>>>(hs, Wq, bq, qp, M_, D_, D_);
    sgemm_bias_kernel<<<gg, 256>>>(hs, Wk, bk, kp, M_, D_, D_);
    sgemm_bias_kernel<<<gg, 256>>>(hs, Wv, bv, vp, M_, D_, D_);

    dim3 ga(S_ / 64, H_, B_);    // (32, 16, 4)
    size_t smA = (size_t)2 * 64 * QPAD * sizeof(float);
    attn_stats_kernel<<<ga, 256, smA>>>(qp, kp, mask, mp, lp);

    size_t smB = (size_t)4 * 64 * QPAD * sizeof(float);  // ~68KB > 48KB default
    cudaFuncSetAttribute(attn_apply_kernel,
                         cudaFuncAttributeMaxDynamicSharedMemorySize, (int)smB);
    attn_apply_kernel<<<ga, 256, smB>>>(qp, kp, vp, mask, mp, lp, attnp, ctxp);

    sgemm_bias_kernel<<<gg, 256>>>(ctxp, Wo, bo, outp, M_, D_, D_);
}

// round 3
// speedup vs baseline: 3.0938x; 3.0938x over previous
#include <cuda_runtime.h>
#include <cuda_bf16.h>
#include <cstdint>

using bf16 = __nv_bfloat16;

namespace {
constexpr int B_  = 4;
constexpr int S_  = 2048;
constexpr int D_  = 1024;
constexpr int H_  = 16;
constexpr int DK_ = 64;
constexpr int M_  = B_ * S_;  // 8192
constexpr long long OUT_ELEMS  = (long long)M_ * D_;
constexpr long long ATTN_ELEMS = (long long)B_ * H_ * S_ * S_;
constexpr float SHIFT = 10.0f;
}

// ------------------------- device scratch (no allocs) -----------------------
__device__ float g_ctx[M_ * D_];
__device__ float g_l[B_ * H_ * S_];
__device__ bf16 g_ahi[M_ * D_], g_alo[M_ * D_];
__device__ bf16 g_qh[M_ * D_],  g_ql[M_ * D_];
__device__ bf16 g_kh[M_ * D_],  g_kl[M_ * D_];
__device__ bf16 g_vh[M_ * D_],  g_vl[M_ * D_];
__device__ bf16 g_ch[M_ * D_],  g_cl[M_ * D_];
__device__ bf16 g_wqh[D_ * D_], g_wql[D_ * D_];
__device__ bf16 g_wkh[D_ * D_], g_wkl[D_ * D_];
__device__ bf16 g_wvh[D_ * D_], g_wvl[D_ * D_];
__device__ bf16 g_woh[D_ * D_], g_wol[D_ * D_];

// ----------------------------- helpers --------------------------------------
__device__ __forceinline__ uint32_t smem_u32(const void* p) {
    uint32_t a;
    asm("{ .reg .u64 t; cvta.to.shared.u64 t, %1; cvt.u32.u64 %0, t; }"
        : "=r"(a) : "l"(p));
    return a;
}

__device__ __forceinline__ void cp16(uint32_t s, const void* g) {
    asm volatile("cp.async.cg.shared.global [%0], [%1], 16;" :: "r"(s), "l"(g));
}
#define CP_COMMIT asm volatile("cp.async.commit_group;" ::: "memory")
#define CP_WAIT0  asm volatile("cp.async.wait_group 0;" ::: "memory")
#define CP_WAIT1  asm volatile("cp.async.wait_group 1;" ::: "memory")

__device__ __forceinline__ void mma16816(float c[4], const uint32_t a[4],
                                         uint32_t b0, uint32_t b1) {
    asm volatile(
        "mma.sync.aligned.m16n8k16.row.col.f32.bf16.bf16.f32 "
        "{%0,%1,%2,%3}, {%4,%5,%6,%7}, {%8,%9}, {%0,%1,%2,%3};"
        : "+f"(c[0]), "+f"(c[1]), "+f"(c[2]), "+f"(c[3])
        : "r"(a[0]), "r"(a[1]), "r"(a[2]), "r"(a[3]), "r"(b0), "r"(b1));
}

__device__ __forceinline__ uint32_t pack2(float x, float y) {
    __nv_bfloat162 t = __floats2bfloat162_rn(x, y);
    return *reinterpret_cast<uint32_t*>(&t);
}

// ---------------------------------------------------------------------------
// fp32 -> bf16 hi/lo split
// ---------------------------------------------------------------------------
__global__ void split_kernel(const float* __restrict__ x,
                             bf16* __restrict__ hi, bf16* __restrict__ lo, int n)
{
    int i = blockIdx.x * blockDim.x + threadIdx.x;
    if (i < n) {
        float v = x[i];
        bf16 h = __float2bfloat16(v);
        hi[i] = h;
        lo[i] = __float2bfloat16(v - __bfloat162float(h));
    }
}

// ---------------------------------------------------------------------------
// ctx scale (1/l) + split to bf16 hi/lo
// ---------------------------------------------------------------------------
__global__ void ctx_split_kernel(const float* __restrict__ ctx,
                                 const float* __restrict__ lrow,
                                 bf16* __restrict__ hi, bf16* __restrict__ lo)
{
    int i = blockIdx.x * blockDim.x + threadIdx.x;
    if (i < M_ * D_) {
        int m = i >> 10;
        int d = i & (D_ - 1);
        int b = m >> 11;
        int s = m & (S_ - 1);
        int h = d >> 6;
        float lv = lrow[((b << 4) + h) * S_ + s];
        float inv = (lv > 0.f) ? (1.f / lv) : 0.f;
        float v = ctx[i] * inv;
        bf16 hh = __float2bfloat16(v);
        hi[i] = hh;
        lo[i] = __float2bfloat16(v - __bfloat162float(hh));
    }
}

// ---------------------------------------------------------------------------
// attn row normalization
// ---------------------------------------------------------------------------
__global__ void norm_attn_kernel(float* __restrict__ attn,
                                 const float* __restrict__ lrow)
{
    long long row = blockIdx.x;
    float lv = lrow[row];
    float inv = (lv > 0.f) ? (1.f / lv) : 0.f;
    float4* p = (float4*)(attn + row * (long long)S_);
#pragma unroll
    for (int it = 0; it < 2; ++it) {
        int i = it * 256 + threadIdx.x;
        float4 v = p[i];
        v.x *= inv; v.y *= inv; v.z *= inv; v.w *= inv;
        p[i] = v;
    }
}

// ---------------------------------------------------------------------------
// Split-bf16 HMMA GEMM: C[8192,1024] = A @ W^T + bias
// Tile 128x128, 8 warps (32m x 64n each), K-chunk 32, 3 split passes.
// Outputs: f32 (Cf) and/or bf16 hi/lo (Chi/Clo).
// ---------------------------------------------------------------------------
__global__ void __launch_bounds__(256) gemm_mma_kernel(
    const bf16* __restrict__ Ahi, const bf16* __restrict__ Alo,
    const bf16* __restrict__ Whi, const bf16* __restrict__ Wlo,
    const float* __restrict__ bias,
    float* __restrict__ Cf, bf16* __restrict__ Chi, bf16* __restrict__ Clo)
{
    constexpr int PA = 40;  // smem pitch (bf16) for 32-wide chunks
    __shared__ __align__(16) bf16 sA[2][128 * PA];
    __shared__ __align__(16) bf16 sB[2][128 * PA];

    const int tid = threadIdx.x;
    const int w = tid >> 5, lane = tid & 31, gid = lane >> 2, tig = lane & 3;
    const int bm = blockIdx.y * 128, bn = blockIdx.x * 128;
    const int m0 = (w >> 1) * 32, n0 = (w & 1) * 64;

    const bf16* Asrc[3] = {Ahi, Alo, Ahi};
    const bf16* Wsrc[3] = {Whi, Whi, Wlo};

    float c[2][8][4] = {};

    auto load_chunk = [&](int t, int buf) {
        int seg = t >> 5, kc = (t & 31) << 5;
        const bf16* As = Asrc[seg];
        const bf16* Ws = Wsrc[seg];
#pragma unroll
        for (int i = 0; i < 2; ++i) {
            int idx = tid * 2 + i;       // 0..511
            int row = idx >> 2, q = idx & 3;
            cp16(smem_u32(&sA[buf][row * PA + q * 8]),
                 As + (size_t)(bm + row) * 1024 + kc + q * 8);
            cp16(smem_u32(&sB[buf][row * PA + q * 8]),
                 Ws + (size_t)(bn + row) * 1024 + kc + q * 8);
        }
    };

    load_chunk(0, 0);
    CP_COMMIT;

    for (int t = 0; t < 96; ++t) {
        int buf = t & 1;
        if (t + 1 < 96) { load_chunk(t + 1, buf ^ 1); CP_COMMIT; CP_WAIT1; }
        else           { CP_WAIT0; }
        __syncthreads();

#pragma unroll
        for (int ks = 0; ks < 32; ks += 16) {
            uint32_t a[2][4];
#pragma unroll
            for (int mi = 0; mi < 2; ++mi) {
                int r = m0 + mi * 16 + gid;
                a[mi][0] = *(const uint32_t*)&sA[buf][r * PA + ks + 2 * tig];
                a[mi][1] = *(const uint32_t*)&sA[buf][(r + 8) * PA + ks + 2 * tig];
                a[mi][2] = *(const uint32_t*)&sA[buf][r * PA + ks + 8 + 2 * tig];
                a[mi][3] = *(const uint32_t*)&sA[buf][(r + 8) * PA + ks + 8 + 2 * tig];
            }
#pragma unroll
            for (int ni = 0; ni < 8; ++ni) {
                int br = n0 + ni * 8 + gid;
                uint32_t b0 = *(const uint32_t*)&sB[buf][br * PA + ks + 2 * tig];
                uint32_t b1 = *(const uint32_t*)&sB[buf][br * PA + ks + 8 + 2 * tig];
                mma16816(c[0][ni], a[0], b0, b1);
                mma16816(c[1][ni], a[1], b0, b1);
            }
        }
        __syncthreads();
    }

    // Epilogue
#pragma unroll
    for (int mi = 0; mi < 2; ++mi) {
#pragma unroll
        for (int ni = 0; ni < 8; ++ni) {
            int r0 = bm + m0 + mi * 16 + gid;
            int col = bn + n0 + ni * 8 + 2 * tig;
            float bv0 = bias[col], bv1 = bias[col + 1];
            float o00 = c[mi][ni][0] + bv0, o01 = c[mi][ni][1] + bv1;
            float o10 = c[mi][ni][2] + bv0, o11 = c[mi][ni][3] + bv1;
            if (Cf) {
                *(float2*)&Cf[(size_t)r0 * 1024 + col] = make_float2(o00, o01);
                *(float2*)&Cf[(size_t)(r0 + 8) * 1024 + col] = make_float2(o10, o11);
            }
            if (Chi) {
                float h00 = __bfloat162float(__float2bfloat16(o00));
                float h01 = __bfloat162float(__float2bfloat16(o01));
                float h10 = __bfloat162float(__float2bfloat16(o10));
                float h11 = __bfloat162float(__float2bfloat16(o11));
                *(uint32_t*)&Chi[(size_t)r0 * 1024 + col]       = pack2(o00, o01);
                *(uint32_t*)&Chi[(size_t)(r0 + 8) * 1024 + col] = pack2(o10, o11);
                *(uint32_t*)&Clo[(size_t)r0 * 1024 + col]       = pack2(o00 - h00, o01 - h01);
                *(uint32_t*)&Clo[(size_t)(r0 + 8) * 1024 + col] = pack2(o10 - h10, o11 - h11);
            }
        }
    }
}

// ---------------------------------------------------------------------------
// One-pass HMMA attention.
// Block: 128 q-rows x (b,h); loops 32 chunks of 64 keys.
// Warps 8: wm = w>>1 (q rows m0=wm*32), wn = w&1 (keys/dk n0=wn*32).
// S = Q@K^T (3 split passes) -> exp -> attn write + P hi/lo staged in smem
// -> ctx += P@V (3 split passes, ldmatrix.trans for V).
// ---------------------------------------------------------------------------
__global__ void __launch_bounds__(256) attn_mma_kernel(
    const bf16* __restrict__ qh, const bf16* __restrict__ ql,
    const bf16* __restrict__ kh, const bf16* __restrict__ kl,
    const bf16* __restrict__ vh, const bf16* __restrict__ vl,
    const int* __restrict__ maskg,
    float* __restrict__ attn, float* __restrict__ ctx, float* __restrict__ lg)
{
    constexpr int P = 72;  // smem pitch (bf16) for 64-wide tiles
    extern __shared__ __align__(16) bf16 dsm[];
    bf16* QH = dsm;                  // 128*72
    bf16* QL = dsm + 9216;
    bf16* KH = dsm + 18432;          // 64*72
    bf16* KL = dsm + 23040;
    bf16* VH = dsm + 27648;
    bf16* VL = dsm + 32256;
    bf16* PH = dsm + 36864;          // 128*72
    bf16* PL = dsm + 46080;
    int*   sMask = (int*)(dsm + 55296);   // 64 ints
    float* sL    = (float*)(sMask + 64);  // 128 floats

    const int tid = threadIdx.x;
    const int w = tid >> 5, lane = tid & 31, gid = lane >> 2, tig = lane & 3;
    const int qt = blockIdx.x, h = blockIdx.y, b = blockIdx.z;
    const int q0 = qt * 128;
    const int m0 = (w >> 1) * 32, n0 = (w & 1) * 32;

    if (tid < 128) sL[tid] = 0.f;

    // Q tiles (hi/lo), 128 rows x 64 cols of head h
    {
        size_t base = (size_t)(b * S_ + q0) * D_ + h * 64;
#pragma unroll
        for (int i = 0; i < 4; ++i) {
            int idx = tid * 4 + i;   // 0..1023
            int row = idx >> 3, qq = idx & 7;
            cp16(smem_u32(&QH[row * P + qq * 8]), qh + base + (size_t)row * D_ + qq * 8);
            cp16(smem_u32(&QL[row * P + qq * 8]), ql + base + (size_t)row * D_ + qq * 8);
        }
        CP_COMMIT;
    }

    float ctxc[2][4][4] = {};
    float lacc[2][2]    = {};

    for (int kt = 0; kt < 32; ++kt) {
        const int kb = kt * 64;
        size_t kbase = (size_t)(b * S_ + kb) * D_ + h * 64;
#pragma unroll
        for (int i = 0; i < 2; ++i) {
            int idx = tid * 2 + i;   // 0..511
            int row = idx >> 3, qq = idx & 7;
            size_t go = kbase + (size_t)row * D_ + qq * 8;
            cp16(smem_u32(&KH[row * P + qq * 8]), kh + go);
            cp16(smem_u32(&KL[row * P + qq * 8]), kl + go);
            cp16(smem_u32(&VH[row * P + qq * 8]), vh + go);
            cp16(smem_u32(&VL[row * P + qq * 8]), vl + go);
        }
        if (tid < 64) sMask[tid] = maskg[b * S_ + kb + tid];
        CP_COMMIT;
        CP_WAIT0;
        __syncthreads();

        // ---- S = Q @ K^T (3 passes over splits) ----
        float sc[2][4][4] = {};
        {
            const bf16* Ab[3] = {QH, QL, QH};
            const bf16* Bb[3] = {KH, KH, KL};
#pragma unroll
            for (int ps = 0; ps < 3; ++ps) {
                const bf16* Q_ = Ab[ps];
                const bf16* K_ = Bb[ps];
#pragma unroll
                for (int ks = 0; ks < 64; ks += 16) {
                    uint32_t a[2][4];
#pragma unroll
                    for (int mi = 0; mi < 2; ++mi) {
                        int r = m0 + mi * 16 + gid;
                        a[mi][0] = *(const uint32_t*)&Q_[r * P + ks + 2 * tig];
                        a[mi][1] = *(const uint32_t*)&Q_[(r + 8) * P + ks + 2 * tig];
                        a[mi][2] = *(const uint32_t*)&Q_[r * P + ks + 8 + 2 * tig];
                        a[mi][3] = *(const uint32_t*)&Q_[(r + 8) * P + ks + 8 + 2 * tig];
                    }
#pragma unroll
                    for (int ni = 0; ni < 4; ++ni) {
                        int br = n0 + ni * 8 + gid;
                        uint32_t b0 = *(const uint32_t*)&K_[br * P + ks + 2 * tig];
                        uint32_t b1 = *(const uint32_t*)&K_[br * P + ks + 8 + 2 * tig];
                        mma16816(sc[0][ni], a[0], b0, b1);
                        mma16816(sc[1][ni], a[1], b0, b1);
                    }
                }
            }
        }

        // ---- exp, attn write, l accum, stage P hi/lo ----
#pragma unroll
        for (int mi = 0; mi < 2; ++mi) {
#pragma unroll
            for (int ni = 0; ni < 4; ++ni) {
                int cc = n0 + ni * 8 + 2 * tig;
                bool k0 = sMask[cc] != 0, k1 = sMask[cc + 1] != 0;
                float p00 = k0 ? __expf(sc[mi][ni][0] * 0.125f - SHIFT) : 0.f;
                float p01 = k1 ? __expf(sc[mi][ni][1] * 0.125f - SHIFT) : 0.f;
                float p10 = k0 ? __expf(sc[mi][ni][2] * 0.125f - SHIFT) : 0.f;
                float p11 = k1 ? __expf(sc[mi][ni][3] * 0.125f - SHIFT) : 0.f;
                lacc[mi][0] += p00 + p01;
                lacc[mi][1] += p10 + p11;
                int r = m0 + mi * 16 + gid;
                if (attn) {
                    size_t arow = ((size_t)((b * H_ + h) * S_) + q0 + r) * S_ + kb + cc;
                    *(float2*)&attn[arow]            = make_float2(p00, p01);
                    *(float2*)&attn[arow + 8 * (size_t)S_] = make_float2(p10, p11);
                }
                float h00 = __bfloat162float(__float2bfloat16(p00));
                float h01 = __bfloat162float(__float2bfloat16(p01));
                float h10 = __bfloat162float(__float2bfloat16(p10));
                float h11 = __bfloat162float(__float2bfloat16(p11));
                *(uint32_t*)&PH[r * P + cc]       = pack2(p00, p01);
                *(uint32_t*)&PH[(r + 8) * P + cc] = pack2(p10, p11);
                *(uint32_t*)&PL[r * P + cc]       = pack2(p00 - h00, p01 - h01);
                *(uint32_t*)&PL[(r + 8) * P + cc] = pack2(p10 - h10, p11 - h11);
            }
        }
        __syncthreads();

        // ---- ctx += P @ V (3 passes; warp covers dk range n0..n0+31) ----
        {
            const bf16* Ab[3] = {PH, PL, PH};
            const bf16* Bb[3] = {VH, VH, VL};
#pragma unroll
            for (int ps = 0; ps < 3; ++ps) {
                const bf16* P_ = Ab[ps];
                const bf16* V_ = Bb[ps];
#pragma unroll
                for (int ks = 0; ks < 64; ks += 16) {
                    uint32_t a[2][4];
#pragma unroll
                    for (int mi = 0; mi < 2; ++mi) {
                        int r = m0 + mi * 16 + gid;
                        a[mi][0] = *(const uint32_t*)&P_[r * P + ks + 2 * tig];
                        a[mi][1] = *(const uint32_t*)&P_[(r + 8) * P + ks + 2 * tig];
                        a[mi][2] = *(const uint32_t*)&P_[r * P + ks + 8 + 2 * tig];
                        a[mi][3] = *(const uint32_t*)&P_[(r + 8) * P + ks + 8 + 2 * tig];
                    }
#pragma unroll
                    for (int ni = 0; ni < 4; ++ni) {
                        int ncol = n0 + ni * 8;   // dk column base
                        uint32_t baddr = smem_u32(&V_[(ks + (lane & 15)) * P + ncol]);
                        uint32_t b0, b1;
                        asm volatile(
                            "ldmatrix.sync.aligned.m8n8.x2.trans.shared.b16 {%0,%1}, [%2];"
                            : "=r"(b0), "=r"(b1) : "r"(baddr));
                        mma16816(ctxc[0][ni], a[0], b0, b1);
                        mma16816(ctxc[1][ni], a[1], b0, b1);
                    }
                }
            }
        }
        __syncthreads();
    }

    // ---- l reduce & write ----
#pragma unroll
    for (int mi = 0; mi < 2; ++mi) {
#pragma unroll
        for (int half = 0; half < 2; ++half) {
            float v = lacc[mi][half];
            v += __shfl_xor_sync(0xffffffffu, v, 1);
            v += __shfl_xor_sync(0xffffffffu, v, 2);
            if (tig == 0)
                atomicAdd(&sL[m0 + mi * 16 + gid + half * 8], v);
        }
    }
    __syncthreads();
    if (tid < 128)
        lg[(size_t)(b * H_ + h) * S_ + q0 + tid] = sL[tid];

    // ---- ctx write (unnormalized f32) ----
#pragma unroll
    for (int mi = 0; mi < 2; ++mi) {
#pragma unroll
        for (int ni = 0; ni < 4; ++ni) {
            int r = q0 + m0 + mi * 16 + gid;
            int col = h * 64 + n0 + ni * 8 + 2 * tig;
            size_t base = ((size_t)(b * S_) + r) * D_ + col;
            *(float2*)&ctx[base] = make_float2(ctxc[mi][ni][0], ctxc[mi][ni][1]);
            *(float2*)&ctx[base + 8 * (size_t)D_] =
                make_float2(ctxc[mi][ni][2], ctxc[mi][ni][3]);
        }
    }
}

// ---------------------------------------------------------------------------
extern "C" void kernel_launch(void* const* d_in, const int* in_sizes, int n_in,
                              void* d_out, int out_size)
{
    const float* hs   = (const float*)d_in[0];
    const int*   mask = (const int*)  d_in[1];
    const float* Wq   = (const float*)d_in[2];
    const float* bq   = (const float*)d_in[3];
    const float* Wk   = (const float*)d_in[4];
    const float* bk   = (const float*)d_in[5];
    const float* Wv   = (const float*)d_in[6];
    const float* bv   = (const float*)d_in[7];
    const float* Wo   = (const float*)d_in[8];
    const float* bo   = (const float*)d_in[9];

    float* outp = (float*)d_out;

    float *ctxp, *lp;
    bf16 *ahi, *alo, *qhp, *qlp, *khp, *klp, *vhp, *vlp, *chp, *clp;
    bf16 *wqh, *wql, *wkh, *wkl, *wvh, *wvl, *woh, *wol;
    cudaGetSymbolAddress((void**)&ctxp, g_ctx);
    cudaGetSymbolAddress((void**)&lp,   g_l);
    cudaGetSymbolAddress((void**)&ahi,  g_ahi);
    cudaGetSymbolAddress((void**)&alo,  g_alo);
    cudaGetSymbolAddress((void**)&qhp,  g_qh);
    cudaGetSymbolAddress((void**)&qlp,  g_ql);
    cudaGetSymbolAddress((void**)&khp,  g_kh);
    cudaGetSymbolAddress((void**)&klp,  g_kl);
    cudaGetSymbolAddress((void**)&vhp,  g_vh);
    cudaGetSymbolAddress((void**)&vlp,  g_vl);
    cudaGetSymbolAddress((void**)&chp,  g_ch);
    cudaGetSymbolAddress((void**)&clp,  g_cl);
    cudaGetSymbolAddress((void**)&wqh,  g_wqh);
    cudaGetSymbolAddress((void**)&wql,  g_wql);
    cudaGetSymbolAddress((void**)&wkh,  g_wkh);
    cudaGetSymbolAddress((void**)&wkl,  g_wkl);
    cudaGetSymbolAddress((void**)&wvh,  g_wvh);
    cudaGetSymbolAddress((void**)&wvl,  g_wvl);
    cudaGetSymbolAddress((void**)&woh,  g_woh);
    cudaGetSymbolAddress((void**)&wol,  g_wol);

    float* attnp = nullptr;
    if ((long long)out_size >= OUT_ELEMS + ATTN_ELEMS)
        attnp = outp + OUT_ELEMS;

    // 1. splits
    split_kernel<<<(M_ * D_ + 255) / 256, 256>>>(hs, ahi, alo, M_ * D_);
    split_kernel<<<(D_ * D_ + 255) / 256, 256>>>(Wq, wqh, wql, D_ * D_);
    split_kernel<<<(D_ * D_ + 255) / 256, 256>>>(Wk, wkh, wkl, D_ * D_);
    split_kernel<<<(D_ * D_ + 255) / 256, 256>>>(Wv, wvh, wvl, D_ * D_);
    split_kernel<<<(D_ * D_ + 255) / 256, 256>>>(Wo, woh, wol, D_ * D_);

    // 2. Q/K/V projections (HMMA, write bf16 hi/lo directly)
    dim3 gg(D_ / 128, M_ / 128);   // (8, 64)
    gemm_mma_kernel<<<gg, 256>>>(ahi, alo, wqh, wql, bq, nullptr, qhp, qlp);
    gemm_mma_kernel<<<gg, 256>>>(ahi, alo, wkh, wkl, bk, nullptr, khp, klp);
    gemm_mma_kernel<<<gg, 256>>>(ahi, alo, wvh, wvl, bv, nullptr, vhp, vlp);

    // 3. one-pass attention
    dim3 ga(S_ / 128, H_, B_);     // (16, 16, 4)
    size_t smA = 55296 * sizeof(bf16) + 64 * sizeof(int) + 128 * sizeof(float);
    cudaFuncSetAttribute(attn_mma_kernel,
                         cudaFuncAttributeMaxDynamicSharedMemorySize, (int)smA);
    attn_mma_kernel<<<ga, 256, smA>>>(qhp, qlp, khp, klp, vhp, vlp, mask,
                                      attnp, ctxp, lp);

    // 4. normalize attn rows
    if (attnp)
        norm_attn_kernel<<<B_ * H_ * S_, 256>>>(attnp, lp);

    // 5. scale + split ctx
    ctx_split_kernel<<<(M_ * D_ + 255) / 256, 256>>>(ctxp, lp, chp, clp);

    // 6. output projection (f32 out + bias)
    gemm_mma_kernel<<<gg, 256>>>(chp, clp, woh, wol, bo, outp, nullptr, nullptr);
}

// round 4
// speedup vs baseline: 3.2549x; 1.0521x over previous
#include <cuda_runtime.h>
#include <cuda_bf16.h>
#include <cstdint>

using bf16 = __nv_bfloat16;

namespace {
constexpr int B_  = 4;
constexpr int S_  = 2048;
constexpr int D_  = 1024;
constexpr int H_  = 16;
constexpr int M_  = B_ * S_;  // 8192
constexpr long long OUT_ELEMS  = (long long)M_ * D_;
constexpr long long ATTN_ELEMS = (long long)B_ * H_ * S_ * S_;
constexpr float SHIFT = 10.0f;
}

// ------------------------- device scratch (no allocs) -----------------------
__device__ float g_ctx[M_ * D_];
__device__ float g_l[B_ * H_ * S_];
__device__ bf16 g_ahi[M_ * D_], g_alo[M_ * D_];
__device__ bf16 g_qh[M_ * D_],  g_ql[M_ * D_];
__device__ bf16 g_kh[M_ * D_],  g_kl[M_ * D_];
__device__ bf16 g_vh[M_ * D_],  g_vl[M_ * D_];
__device__ bf16 g_ch[M_ * D_],  g_cl[M_ * D_];
__device__ bf16 g_wqh[D_ * D_], g_wql[D_ * D_];
__device__ bf16 g_wkh[D_ * D_], g_wkl[D_ * D_];
__device__ bf16 g_wvh[D_ * D_], g_wvl[D_ * D_];
__device__ bf16 g_woh[D_ * D_], g_wol[D_ * D_];

// ----------------------------- helpers --------------------------------------
__device__ __forceinline__ uint32_t smem_u32(const void* p) {
    uint32_t a;
    asm("{ .reg .u64 t; cvta.to.shared.u64 t, %1; cvt.u32.u64 %0, t; }"
        : "=r"(a) : "l"(p));
    return a;
}

__device__ __forceinline__ void cp16(uint32_t s, const void* g) {
    asm volatile("cp.async.cg.shared.global [%0], [%1], 16;" :: "r"(s), "l"(g));
}
#define CP_COMMIT asm volatile("cp.async.commit_group;" ::: "memory")
#define CP_WAIT0  asm volatile("cp.async.wait_group 0;" ::: "memory")
#define CP_WAIT1  asm volatile("cp.async.wait_group 1;" ::: "memory")

#define LDSM_X4(r0, r1, r2, r3, addr) \
    asm volatile("ldmatrix.sync.aligned.m8n8.x4.shared.b16 {%0,%1,%2,%3}, [%4];" \
                 : "=r"(r0), "=r"(r1), "=r"(r2), "=r"(r3) : "r"(addr))

__device__ __forceinline__ void mma16816(float c[4], const uint32_t a[4],
                                         uint32_t b0, uint32_t b1) {
    asm volatile(
        "mma.sync.aligned.m16n8k16.row.col.f32.bf16.bf16.f32 "
        "{%0,%1,%2,%3}, {%4,%5,%6,%7}, {%8,%9}, {%0,%1,%2,%3};"
        : "+f"(c[0]), "+f"(c[1]), "+f"(c[2]), "+f"(c[3])
        : "r"(a[0]), "r"(a[1]), "r"(a[2]), "r"(a[3]), "r"(b0), "r"(b1));
}

__device__ __forceinline__ uint32_t pack2(float x, float y) {
    __nv_bfloat162 t = __floats2bfloat162_rn(x, y);
    return *reinterpret_cast<uint32_t*>(&t);
}

// ---------------------------------------------------------------------------
__global__ void split_kernel(const float* __restrict__ x,
                             bf16* __restrict__ hi, bf16* __restrict__ lo, int n)
{
    int i = blockIdx.x * blockDim.x + threadIdx.x;
    if (i < n) {
        float v = x[i];
        bf16 h = __float2bfloat16(v);
        hi[i] = h;
        lo[i] = __float2bfloat16(v - __bfloat162float(h));
    }
}

__global__ void ctx_split_kernel(const float* __restrict__ ctx,
                                 const float* __restrict__ lrow,
                                 bf16* __restrict__ hi, bf16* __restrict__ lo)
{
    int i = blockIdx.x * blockDim.x + threadIdx.x;
    if (i < M_ * D_) {
        int m = i >> 10;
        int d = i & (D_ - 1);
        int b = m >> 11;
        int s = m & (S_ - 1);
        int h = d >> 6;
        float lv = lrow[((b << 4) + h) * S_ + s];
        float inv = (lv > 0.f) ? (1.f / lv) : 0.f;
        float v = ctx[i] * inv;
        bf16 hh = __float2bfloat16(v);
        hi[i] = hh;
        lo[i] = __float2bfloat16(v - __bfloat162float(hh));
    }
}

__global__ void norm_attn_kernel(float* __restrict__ attn,
                                 const float* __restrict__ lrow)
{
    long long row = blockIdx.x;
    float lv = lrow[row];
    float inv = (lv > 0.f) ? (1.f / lv) : 0.f;
    float4* p = (float4*)(attn + row * (long long)S_);
#pragma unroll
    for (int it = 0; it < 2; ++it) {
        int i = it * 256 + threadIdx.x;
        float4 v = p[i];
        v.x *= inv; v.y *= inv; v.z *= inv; v.w *= inv;
        p[i] = v;
    }
}

// ---------------------------------------------------------------------------
// Split-bf16 HMMA GEMM, 128x128 tile, 3-stage cp.async pipeline, ldmatrix.
// ---------------------------------------------------------------------------
struct GemmArgs {
    const bf16 *Ahi, *Alo, *Wh, *Wl;
    const float* bias;
    float* Cf;
    bf16 *Ch, *Cl;
};
struct GemmArgs3 { GemmArgs a[3]; };

__global__ void __launch_bounds__(256, 2) gemm_mma_kernel(GemmArgs3 args)
{
    constexpr int PA = 40;      // smem pitch (bf16)
    constexpr int BUFE = 128 * PA;   // 5120 bf16 per tile buffer
    extern __shared__ __align__(16) bf16 gsm[];   // 3 stages x (A + B)

    const GemmArgs ga = args.a[blockIdx.z];

    const int tid = threadIdx.x;
    const int w = tid >> 5, lane = tid & 31, gid = lane >> 2, tig = lane & 3;
    const int bm = blockIdx.y * 128, bn = blockIdx.x * 128;
    const int m0 = (w >> 1) * 32, n0 = (w & 1) * 64;

    const bf16* Asrc[3] = {ga.Ahi, ga.Alo, ga.Ahi};
    const bf16* Wsrc[3] = {ga.Wh,  ga.Wh,  ga.Wl};

    float c[2][8][4] = {};

    auto load_chunk = [&](int t, int buf) {
        int seg = t >> 5, kc = (t & 31) << 5;
        const bf16* As = Asrc[seg];
        const bf16* Ws = Wsrc[seg];
        bf16* sAb = gsm + buf * (2 * BUFE);
        bf16* sBb = sAb + BUFE;
#pragma unroll
        for (int i = 0; i < 2; ++i) {
            int idx = tid * 2 + i;       // 0..511
            int row = idx >> 2, q = idx & 3;
            cp16(smem_u32(&sAb[row * PA + q * 8]),
                 As + (size_t)(bm + row) * 1024 + kc + q * 8);
            cp16(smem_u32(&sBb[row * PA + q * 8]),
                 Ws + (size_t)(bn + row) * 1024 + kc + q * 8);
        }
    };

    load_chunk(0, 0); CP_COMMIT;
    load_chunk(1, 1); CP_COMMIT;

    for (int t = 0; t < 96; ++t) {
        if (t + 2 < 96) { CP_WAIT1; } else { CP_WAIT0; }
        __syncthreads();
        if (t + 2 < 96) { load_chunk(t + 2, (t + 2) % 3); CP_COMMIT; }

        const bf16* sAb = gsm + (t % 3) * (2 * BUFE);
        const bf16* sBb = sAb + BUFE;

#pragma unroll
        for (int ks = 0; ks < 32; ks += 16) {
            uint32_t a[2][4];
#pragma unroll
            for (int mi = 0; mi < 2; ++mi) {
                uint32_t ad = smem_u32(
                    &sAb[(m0 + mi * 16 + (lane & 15)) * PA + ks + ((lane >> 4) << 3)]);
                LDSM_X4(a[mi][0], a[mi][1], a[mi][2], a[mi][3], ad);
            }
#pragma unroll
            for (int p = 0; p < 4; ++p) {
                int nbase = n0 + p * 16;
                int br = nbase + (lane & 7) + ((lane >> 4) << 3);
                int bc = ks + (((lane >> 3) & 1) << 3);
                uint32_t b0, b1, b2, b3;
                LDSM_X4(b0, b1, b2, b3, smem_u32(&sBb[br * PA + bc]));
                mma16816(c[0][2 * p],     a[0], b0, b1);
                mma16816(c[1][2 * p],     a[1], b0, b1);
                mma16816(c[0][2 * p + 1], a[0], b2, b3);
                mma16816(c[1][2 * p + 1], a[1], b2, b3);
            }
        }
        __syncthreads();
    }

    // Epilogue
#pragma unroll
    for (int mi = 0; mi < 2; ++mi) {
#pragma unroll
        for (int ni = 0; ni < 8; ++ni) {
            int r0 = bm + m0 + mi * 16 + gid;
            int col = bn + n0 + ni * 8 + 2 * tig;
            float bv0 = ga.bias[col], bv1 = ga.bias[col + 1];
            float o00 = c[mi][ni][0] + bv0, o01 = c[mi][ni][1] + bv1;
            float o10 = c[mi][ni][2] + bv0, o11 = c[mi][ni][3] + bv1;
            if (ga.Cf) {
                *(float2*)&ga.Cf[(size_t)r0 * 1024 + col] = make_float2(o00, o01);
                *(float2*)&ga.Cf[(size_t)(r0 + 8) * 1024 + col] = make_float2(o10, o11);
            }
            if (ga.Ch) {
                float h00 = __bfloat162float(__float2bfloat16(o00));
                float h01 = __bfloat162float(__float2bfloat16(o01));
                float h10 = __bfloat162float(__float2bfloat16(o10));
                float h11 = __bfloat162float(__float2bfloat16(o11));
                *(uint32_t*)&ga.Ch[(size_t)r0 * 1024 + col]       = pack2(o00, o01);
                *(uint32_t*)&ga.Ch[(size_t)(r0 + 8) * 1024 + col] = pack2(o10, o11);
                *(uint32_t*)&ga.Cl[(size_t)r0 * 1024 + col]       = pack2(o00 - h00, o01 - h01);
                *(uint32_t*)&ga.Cl[(size_t)(r0 + 8) * 1024 + col] = pack2(o10 - h10, o11 - h11);
            }
        }
    }
}

// ---------------------------------------------------------------------------
// One-pass HMMA attention with double-buffered K/V prefetch.
// ---------------------------------------------------------------------------
__global__ void __launch_bounds__(256) attn_mma_kernel(
    const bf16* __restrict__ qh, const bf16* __restrict__ ql,
    const bf16* __restrict__ kh, const bf16* __restrict__ kl,
    const bf16* __restrict__ vh, const bf16* __restrict__ vl,
    const int* __restrict__ maskg,
    float* __restrict__ attn, float* __restrict__ ctx, float* __restrict__ lg)
{
    constexpr int P = 72;
    constexpr int KVBUF = 4 * 64 * P;   // 18432 bf16 per stage (KH,KL,VH,VL)
    extern __shared__ __align__(16) bf16 dsm[];
    bf16* QH = dsm;                      // 128*72
    bf16* QL = dsm + 9216;
    bf16* KV0 = dsm + 18432;             // 2 stages
    bf16* PH = dsm + 18432 + 2 * KVBUF;  // 55296
    bf16* PL = PH + 9216;
    int*   sMask = (int*)(PL + 9216);    // 2 x 64 ints
    float* sL    = (float*)(sMask + 128);

    const int tid = threadIdx.x;
    const int w = tid >> 5, lane = tid & 31, gid = lane >> 2, tig = lane & 3;
    const int qt = blockIdx.x, h = blockIdx.y, b = blockIdx.z;
    const int q0 = qt * 128;
    const int m0 = (w >> 1) * 32, n0 = (w & 1) * 32;

    if (tid < 128) sL[tid] = 0.f;

    // Q tiles (hi/lo)
    {
        size_t base = (size_t)(b * S_ + q0) * D_ + h * 64;
#pragma unroll
        for (int i = 0; i < 4; ++i) {
            int idx = tid * 4 + i;
            int row = idx >> 3, qq = idx & 7;
            cp16(smem_u32(&QH[row * P + qq * 8]), qh + base + (size_t)row * D_ + qq * 8);
            cp16(smem_u32(&QL[row * P + qq * 8]), ql + base + (size_t)row * D_ + qq * 8);
        }
        CP_COMMIT;
    }

    auto load_kv = [&](int kt, int buf) {
        const int kb = kt * 64;
        size_t kbase = (size_t)(b * S_ + kb) * D_ + h * 64;
        bf16* KH = KV0 + buf * KVBUF;
        bf16* KL = KH + 4608;
        bf16* VH = KH + 9216;
        bf16* VL = KH + 13824;
#pragma unroll
        for (int i = 0; i < 2; ++i) {
            int idx = tid * 2 + i;
            int row = idx >> 3, qq = idx & 7;
            size_t go = kbase + (size_t)row * D_ + qq * 8;
            cp16(smem_u32(&KH[row * P + qq * 8]), kh + go);
            cp16(smem_u32(&KL[row * P + qq * 8]), kl + go);
            cp16(smem_u32(&VH[row * P + qq * 8]), vh + go);
            cp16(smem_u32(&VL[row * P + qq * 8]), vl + go);
        }
        if (tid < 16)
            cp16(smem_u32(&sMask[buf * 64 + tid * 4]), maskg + b * S_ + kb + tid * 4);
    };

    load_kv(0, 0); CP_COMMIT;

    float ctxc[2][4][4] = {};
    float lacc[2][2]    = {};

    for (int kt = 0; kt < 32; ++kt) {
        const int kb = kt * 64;
        const int buf = kt & 1;
        if (kt + 1 < 32) { load_kv(kt + 1, buf ^ 1); CP_COMMIT; CP_WAIT1; }
        else             { CP_WAIT0; }
        __syncthreads();

        const bf16* KH = KV0 + buf * KVBUF;
        const bf16* KL = KH + 4608;
        const bf16* VH = KH + 9216;
        const bf16* VL = KH + 13824;
        const int* mk = sMask + buf * 64;

        // ---- S = Q @ K^T (3 split passes) ----
        float sc[2][4][4] = {};
        {
            const bf16* Ab[3] = {QH, QL, QH};
            const bf16* Bb[3] = {KH, KH, KL};
#pragma unroll
            for (int ps = 0; ps < 3; ++ps) {
                const bf16* Q_ = Ab[ps];
                const bf16* K_ = Bb[ps];
#pragma unroll
                for (int ks = 0; ks < 64; ks += 16) {
                    uint32_t a[2][4];
#pragma unroll
                    for (int mi = 0; mi < 2; ++mi) {
                        uint32_t ad = smem_u32(
                            &Q_[(m0 + mi * 16 + (lane & 15)) * P + ks + ((lane >> 4) << 3)]);
                        LDSM_X4(a[mi][0], a[mi][1], a[mi][2], a[mi][3], ad);
                    }
#pragma unroll
                    for (int p = 0; p < 2; ++p) {
                        int nbase = n0 + p * 16;
                        int br = nbase + (lane & 7) + ((lane >> 4) << 3);
                        int bc = ks + (((lane >> 3) & 1) << 3);
                        uint32_t b0, b1, b2, b3;
                        LDSM_X4(b0, b1, b2, b3, smem_u32(&K_[br * P + bc]));
                        mma16816(sc[0][2 * p],     a[0], b0, b1);
                        mma16816(sc[1][2 * p],     a[1], b0, b1);
                        mma16816(sc[0][2 * p + 1], a[0], b2, b3);
                        mma16816(sc[1][2 * p + 1], a[1], b2, b3);
                    }
                }
            }
        }

        // ---- exp, attn write, l accum, stage P hi/lo ----
#pragma unroll
        for (int mi = 0; mi < 2; ++mi) {
#pragma unroll
            for (int ni = 0; ni < 4; ++ni) {
                int cc = n0 + ni * 8 + 2 * tig;
                bool k0 = mk[cc] != 0, k1 = mk[cc + 1] != 0;
                float p00 = k0 ? __expf(sc[mi][ni][0] * 0.125f - SHIFT) : 0.f;
                float p01 = k1 ? __expf(sc[mi][ni][1] * 0.125f - SHIFT) : 0.f;
                float p10 = k0 ? __expf(sc[mi][ni][2] * 0.125f - SHIFT) : 0.f;
                float p11 = k1 ? __expf(sc[mi][ni][3] * 0.125f - SHIFT) : 0.f;
                lacc[mi][0] += p00 + p01;
                lacc[mi][1] += p10 + p11;
                int r = m0 + mi * 16 + gid;
                if (attn) {
                    size_t arow = ((size_t)((b * H_ + h) * S_) + q0 + r) * S_ + kb + cc;
                    *(float2*)&attn[arow]                  = make_float2(p00, p01);
                    *(float2*)&attn[arow + 8 * (size_t)S_] = make_float2(p10, p11);
                }
                float h00 = __bfloat162float(__float2bfloat16(p00));
                float h01 = __bfloat162float(__float2bfloat16(p01));
                float h10 = __bfloat162float(__float2bfloat16(p10));
                float h11 = __bfloat162float(__float2bfloat16(p11));
                *(uint32_t*)&PH[r * P + cc]       = pack2(p00, p01);
                *(uint32_t*)&PH[(r + 8) * P + cc] = pack2(p10, p11);
                *(uint32_t*)&PL[r * P + cc]       = pack2(p00 - h00, p01 - h01);
                *(uint32_t*)&PL[(r + 8) * P + cc] = pack2(p10 - h10, p11 - h11);
            }
        }
        __syncthreads();

        // ---- ctx += P @ V (3 split passes) ----
        {
            const bf16* Ab[3] = {PH, PL, PH};
            const bf16* Bb[3] = {VH, VH, VL};
#pragma unroll
            for (int ps = 0; ps < 3; ++ps) {
                const bf16* P_ = Ab[ps];
                const bf16* V_ = Bb[ps];
#pragma unroll
                for (int ks = 0; ks < 64; ks += 16) {
                    uint32_t a[2][4];
#pragma unroll
                    for (int mi = 0; mi < 2; ++mi) {
                        uint32_t ad = smem_u32(
                            &P_[(m0 + mi * 16 + (lane & 15)) * P + ks + ((lane >> 4) << 3)]);
                        LDSM_X4(a[mi][0], a[mi][1], a[mi][2], a[mi][3], ad);
                    }
#pragma unroll
                    for (int ni = 0; ni < 4; ++ni) {
                        int ncol = n0 + ni * 8;
                        uint32_t baddr = smem_u32(&V_[(ks + (lane & 15)) * P + ncol]);
                        uint32_t b0, b1;
                        asm volatile(
                            "ldmatrix.sync.aligned.m8n8.x2.trans.shared.b16 {%0,%1}, [%2];"
                            : "=r"(b0), "=r"(b1) : "r"(baddr));
                        mma16816(ctxc[0][ni], a[0], b0, b1);
                        mma16816(ctxc[1][ni], a[1], b0, b1);
                    }
                }
            }
        }
        __syncthreads();
    }

    // ---- l reduce & write ----
#pragma unroll
    for (int mi = 0; mi < 2; ++mi) {
#pragma unroll
        for (int half = 0; half < 2; ++half) {
            float v = lacc[mi][half];
            v += __shfl_xor_sync(0xffffffffu, v, 1);
            v += __shfl_xor_sync(0xffffffffu, v, 2);
            if (tig == 0)
                atomicAdd(&sL[m0 + mi * 16 + gid + half * 8], v);
        }
    }
    __syncthreads();
    if (tid < 128)
        lg[(size_t)(b * H_ + h) * S_ + q0 + tid] = sL[tid];

    // ---- ctx write (unnormalized f32) ----
#pragma unroll
    for (int mi = 0; mi < 2; ++mi) {
#pragma unroll
        for (int ni = 0; ni < 4; ++ni) {
            int r = q0 + m0 + mi * 16 + gid;
            int col = h * 64 + n0 + ni * 8 + 2 * tig;
            size_t base = ((size_t)(b * S_) + r) * D_ + col;
            *(float2*)&ctx[base] = make_float2(ctxc[mi][ni][0], ctxc[mi][ni][1]);
            *(float2*)&ctx[base + 8 * (size_t)D_] =
                make_float2(ctxc[mi][ni][2], ctxc[mi][ni][3]);
        }
    }
}

// ---------------------------------------------------------------------------
extern "C" void kernel_launch(void* const* d_in, const int* in_sizes, int n_in,
                              void* d_out, int out_size)
{
    const float* hs   = (const float*)d_in[0];
    const int*   mask = (const int*)  d_in[1];
    const float* Wq   = (const float*)d_in[2];
    const float* bq   = (const float*)d_in[3];
    const float* Wk   = (const float*)d_in[4];
    const float* bk   = (const float*)d_in[5];
    const float* Wv   = (const float*)d_in[6];
    const float* bv   = (const float*)d_in[7];
    const float* Wo   = (const float*)d_in[8];
    const float* bo   = (const float*)d_in[9];

    float* outp = (float*)d_out;

    float *ctxp, *lp;
    bf16 *ahi, *alo, *qhp, *qlp, *khp, *klp, *vhp, *vlp, *chp, *clp;
    bf16 *wqh, *wql, *wkh, *wkl, *wvh, *wvl, *woh, *wol;
    cudaGetSymbolAddress((void**)&ctxp, g_ctx);
    cudaGetSymbolAddress((void**)&lp,   g_l);
    cudaGetSymbolAddress((void**)&ahi,  g_ahi);
    cudaGetSymbolAddress((void**)&alo,  g_alo);
    cudaGetSymbolAddress((void**)&qhp,  g_qh);
    cudaGetSymbolAddress((void**)&qlp,  g_ql);
    cudaGetSymbolAddress((void**)&khp,  g_kh);
    cudaGetSymbolAddress((void**)&klp,  g_kl);
    cudaGetSymbolAddress((void**)&vhp,  g_vh);
    cudaGetSymbolAddress((void**)&vlp,  g_vl);
    cudaGetSymbolAddress((void**)&chp,  g_ch);
    cudaGetSymbolAddress((void**)&clp,  g_cl);
    cudaGetSymbolAddress((void**)&wqh,  g_wqh);
    cudaGetSymbolAddress((void**)&wql,  g_wql);
    cudaGetSymbolAddress((void**)&wkh,  g_wkh);
    cudaGetSymbolAddress((void**)&wkl,  g_wkl);
    cudaGetSymbolAddress((void**)&wvh,  g_wvh);
    cudaGetSymbolAddress((void**)&wvl,  g_wvl);
    cudaGetSymbolAddress((void**)&woh,  g_woh);
    cudaGetSymbolAddress((void**)&wol,  g_wol);

    float* attnp = nullptr;
    if ((long long)out_size >= OUT_ELEMS + ATTN_ELEMS)
        attnp = outp + OUT_ELEMS;

    // 1. splits
    split_kernel<<<(M_ * D_ + 255) / 256, 256>>>(hs, ahi, alo, M_ * D_);
    split_kernel<<<(D_ * D_ + 255) / 256, 256>>>(Wq, wqh, wql, D_ * D_);
    split_kernel<<<(D_ * D_ + 255) / 256, 256>>>(Wk, wkh, wkl, D_ * D_);
    split_kernel<<<(D_ * D_ + 255) / 256, 256>>>(Wv, wvh, wvl, D_ * D_);
    split_kernel<<<(D_ * D_ + 255) / 256, 256>>>(Wo, woh, wol, D_ * D_);

    const int gemm_smem = 3 * 2 * 128 * 40 * (int)sizeof(bf16);   // 61440
    cudaFuncSetAttribute(gemm_mma_kernel,
                         cudaFuncAttributeMaxDynamicSharedMemorySize, gemm_smem);

    // 2. fused Q/K/V projections
    {
        GemmArgs3 a3;
        a3.a[0] = {ahi, alo, wqh, wql, bq, nullptr, qhp, qlp};
        a3.a[1] = {ahi, alo, wkh, wkl, bk, nullptr, khp, klp};
        a3.a[2] = {ahi, alo, wvh, wvl, bv, nullptr, vhp, vlp};
        dim3 gg(D_ / 128, M_ / 128, 3);
        gemm_mma_kernel<<<gg, 256, gemm_smem>>>(a3);
    }

    // 3. one-pass attention (double-buffered KV)
    {
        dim3 ga(S_ / 128, H_, B_);
        int smA = (18432 + 2 * 18432 + 2 * 9216) * (int)sizeof(bf16)
                  + 128 * (int)sizeof(int) + 128 * (int)sizeof(float);
        cudaFuncSetAttribute(attn_mma_kernel,
                             cudaFuncAttributeMaxDynamicSharedMemorySize, smA);
        attn_mma_kernel<<<ga, 256, smA>>>(qhp, qlp, khp, klp, vhp, vlp, mask,
                                          attnp, ctxp, lp);
    }

    // 4. normalize attn rows
    if (attnp)
        norm_attn_kernel<<<B_ * H_ * S_, 256>>>(attnp, lp);

    // 5. scale + split ctx
    ctx_split_kernel<<<(M_ * D_ + 255) / 256, 256>>>(ctxp, lp, chp, clp);

    // 6. output projection (f32 out + bias)
    {
        GemmArgs3 a3;
        a3.a[0] = {chp, clp, woh, wol, bo, outp, nullptr, nullptr};
        dim3 gg(D_ / 128, M_ / 128, 1);
        gemm_mma_kernel<<<gg, 256, gemm_smem>>>(a3);
    }
}